// round 5
// baseline (speedup 1.0000x reference)
#include <cuda_runtime.h>
#include <cfloat>
#include <math.h>

#define Cdim 256
#define Hdim 128
#define Wdim 128
#define HW   16384
#define Bdim 8
#define NTK  128        // tiles per batch = rows (128 px each)
#define PXT  128        // pixels per tile (one full row)

// ---------------- scratch (device globals) ----------------
__device__ float g_u[Cdim];              // v_w^T w3
__device__ float g_t3bias;               // w3 . v_b
__device__ float g_t3s[Bdim*HW];         // t3 per pixel
__device__ float g_Mt[Bdim*NTK];
__device__ float g_Zt[Bdim*NTK];
__device__ float g_ah[Bdim*Hdim];        // h attention (exact, from K1)
__device__ float g_aw[Bdim*Wdim];        // w attention
__device__ float g_wpm[Bdim*NTK*Wdim];   // per-tile column max partial
__device__ float g_wps[Bdim*NTK*Wdim];   // per-tile column sum partial
__device__ float g_xkp[Bdim*NTK*Cdim];   // per-tile unnormalized xk partial
__device__ float g_cf[Bdim*Cdim];        // channel_fea

// ---------------- helpers ----------------
__device__ __forceinline__ float warpMax(float v){
  #pragma unroll
  for (int o=16;o;o>>=1) v = fmaxf(v, __shfl_xor_sync(0xffffffffu, v, o));
  return v;
}
__device__ __forceinline__ float warpSum(float v){
  #pragma unroll
  for (int o=16;o;o>>=1) v += __shfl_xor_sync(0xffffffffu, v, o);
  return v;
}
__device__ __forceinline__ float sigmoidf_(float x){ return 1.f/(1.f+expf(-x)); }

// ---------------- K0: precompute u, t3bias ----------------
__global__ __launch_bounds__(256)
void k0_init(const float* __restrict__ vw, const float* __restrict__ vb,
             const float* __restrict__ w3){
  int t = threadIdx.x;
  float u = 0.f;
  #pragma unroll 8
  for (int o=0;o<Cdim;o++) u = fmaf(w3[o], vw[o*Cdim + t], u);
  g_u[t] = u;
  if (t==0){
    float tb = 0.f;
    for (int o=0;o<Cdim;o++) tb = fmaf(w3[o], vb[o], tb);
    g_t3bias = tb;
  }
}

// ---------------- K1: fused main pass, x read ONCE (smem-staged tile) -------
// grid (NTK, Bdim), 512 thr, dynamic smem.
// Tile = one full row: 256 channels x 128 px = 128 KB staged in smem.
// Warp w (16 warps) handles channels [16w,16w+16), lane = pixel quad (32 f4).
#define K1_SMEM (131072 + 4*8192 + 2048 + 512)
__global__ __launch_bounds__(512, 1)
void k1_main(const float* __restrict__ x, const float* __restrict__ kwp,
             const float* __restrict__ kbp,
             const float* __restrict__ w1, const float* __restrict__ b1){
  extern __shared__ char smem[];
  float4* s_x  = (float4*)smem;                       // [256][32] f4 : 131072
  float4* s_lp = (float4*)(smem + 131072);            // [16][32]     : 8192
  float4* s_tp = (float4*)(smem + 131072 + 8192);
  float4* s_pm = (float4*)(smem + 131072 + 2*8192);
  float4* s_ps = (float4*)(smem + 131072 + 3*8192);
  float*  s_kw = (float*) (smem + 131072 + 4*8192);   // 1024
  float*  s_u  = (float*) (smem + 131072 + 4*8192 + 1024);
  float4* s_e  = (float4*)(smem + 131072 + 4*8192 + 2048); // [32] f4 : 512

  const int jt = blockIdx.x, b = blockIdx.y;
  const int t = threadIdx.x, w = t>>5, lane = t&31;

  if (t < Cdim){ s_kw[t] = kwp[t]; s_u[t] = g_u[t]; }
  __syncthreads();

  // ---- pass A: stage tile + accumulate partials ----
  const float* xb = x + ((size_t)(b*Cdim + 16*w))*HW + jt*PXT + 4*lane;
  float4 aL = make_float4(0,0,0,0), aT = make_float4(0,0,0,0);
  float4 pm = make_float4(-FLT_MAX,-FLT_MAX,-FLT_MAX,-FLT_MAX);
  float4 ps = make_float4(0,0,0,0);
  #pragma unroll
  for (int c16=0;c16<16;c16++){
    int c = 16*w + c16;
    float4 xv = *(const float4*)(xb + (size_t)c16*HW);
    s_x[c*32 + lane] = xv;
    float kw = s_kw[c], uc = s_u[c];
    aL.x = fmaf(kw, xv.x, aL.x); aL.y = fmaf(kw, xv.y, aL.y);
    aL.z = fmaf(kw, xv.z, aL.z); aL.w = fmaf(kw, xv.w, aL.w);
    aT.x = fmaf(uc, xv.x, aT.x); aT.y = fmaf(uc, xv.y, aT.y);
    aT.z = fmaf(uc, xv.z, aT.z); aT.w = fmaf(uc, xv.w, aT.w);
    pm.x = fmaxf(pm.x, xv.x); pm.y = fmaxf(pm.y, xv.y);
    pm.z = fmaxf(pm.z, xv.z); pm.w = fmaxf(pm.w, xv.w);
    ps.x += xv.x; ps.y += xv.y; ps.z += xv.z; ps.w += xv.w;
  }
  s_lp[w*32 + lane] = aL; s_tp[w*32 + lane] = aT;
  s_pm[w*32 + lane] = pm; s_ps[w*32 + lane] = ps;
  __syncthreads();

  // ---- warp 0: logits, t3, pools, softmax stats ----
  if (w == 0){
    float4 l  = make_float4(0,0,0,0), tv = make_float4(0,0,0,0);
    float4 cm = make_float4(-FLT_MAX,-FLT_MAX,-FLT_MAX,-FLT_MAX);
    float4 cs = make_float4(0,0,0,0);
    #pragma unroll
    for (int i=0;i<16;i++){
      float4 a = s_lp[i*32+lane], bb = s_tp[i*32+lane];
      float4 m = s_pm[i*32+lane], ss = s_ps[i*32+lane];
      l.x += a.x; l.y += a.y; l.z += a.z; l.w += a.w;
      tv.x += bb.x; tv.y += bb.y; tv.z += bb.z; tv.w += bb.w;
      cm.x = fmaxf(cm.x,m.x); cm.y = fmaxf(cm.y,m.y);
      cm.z = fmaxf(cm.z,m.z); cm.w = fmaxf(cm.w,m.w);
      cs.x += ss.x; cs.y += ss.y; cs.z += ss.z; cs.w += ss.w;
    }
    const float kb = kbp[0], tb = g_t3bias;
    l.x += kb; l.y += kb; l.z += kb; l.w += kb;
    tv.x += tb; tv.y += tb; tv.z += tb; tv.w += tb;
    *(float4*)(g_t3s + (size_t)b*HW + jt*PXT + 4*lane) = tv;

    // w-pool partials (per column quad)
    *(float4*)(g_wpm + ((size_t)(b*NTK+jt))*Wdim + 4*lane) = cm;
    *(float4*)(g_wps + ((size_t)(b*NTK+jt))*Wdim + 4*lane) = cs;

    // h-pool: exact over full row x all channels
    float rm = fmaxf(fmaxf(cm.x,cm.y), fmaxf(cm.z,cm.w));
    float rs = cs.x+cs.y+cs.z+cs.w;
    rm = warpMax(rm); rs = warpSum(rs);
    if (lane==0)
      g_ah[b*Hdim + jt] = sigmoidf_(w1[0]*rm + w1[1]*(rs*(1.f/32768.f)) + b1[0]);

    // tile softmax
    float lm = fmaxf(fmaxf(l.x,l.y), fmaxf(l.z,l.w));
    float M = warpMax(lm);
    float4 e;
    e.x = expf(l.x-M); e.y = expf(l.y-M); e.z = expf(l.z-M); e.w = expf(l.w-M);
    s_e[lane] = e;
    float z = warpSum(e.x+e.y+e.z+e.w);
    if (lane==0){ g_Mt[b*NTK + jt] = M; g_Zt[b*NTK + jt] = z; }
  }
  __syncthreads();

  // ---- pass B: xk partials from SMEM ----
  float4 e = s_e[lane];
  #pragma unroll
  for (int c16=0;c16<16;c16++){
    int c = 16*w + c16;
    float4 xv = s_x[c*32 + lane];
    float acc = xv.x*e.x + xv.y*e.y;
    acc = fmaf(xv.z, e.z, acc); acc = fmaf(xv.w, e.w, acc);
    acc = warpSum(acc);
    if (lane==0) g_xkp[((size_t)(b*NTK+jt))*Cdim + c] = acc;
  }
}

// ---------------- K2: per-batch combine: aw + alpha + xk + cf ----------------
// grid (Bdim), 256 thr
__global__ __launch_bounds__(256)
void k2_combine(const float* __restrict__ vw, const float* __restrict__ vb,
                const float* __restrict__ w2, const float* __restrict__ b2){
  const int b = blockIdx.x, t = threadIdx.x;
  const int warp = t>>5, lane = t&31;
  __shared__ float s_m[256], s_s2[256];
  __shared__ float s_alpha[NTK], s_xk[Cdim], s_red[8];
  __shared__ float sM, sZ;

  // --- w attention: 2 threads per column, 64 tiles each ---
  {
    const int col = t & 127, part = t >> 7;
    float m = -FLT_MAX, s = 0.f;
    #pragma unroll 8
    for (int j=0;j<64;j++){
      size_t idx = ((size_t)(b*NTK + part*64 + j))*Wdim + col;
      m = fmaxf(m, g_wpm[idx]);
      s += g_wps[idx];
    }
    s_m[t] = m; s_s2[t] = s;
  }
  __syncthreads();
  if (t < 128){
    float mm = fmaxf(s_m[t], s_m[128+t]);
    float ss = s_s2[t] + s_s2[128+t];
    g_aw[b*Wdim + t] = sigmoidf_(w2[0]*mm + w2[1]*(ss*(1.f/32768.f)) + b2[0]);
  }

  // --- alpha over 128 tiles ---
  float m = (t < NTK) ? g_Mt[b*NTK + t] : -FLT_MAX;
  float mm = warpMax(m);
  if (lane==0) s_red[warp] = mm;
  __syncthreads();
  if (t==0){
    float M = s_red[0];
    #pragma unroll
    for (int r=1;r<8;r++) M = fmaxf(M, s_red[r]);
    sM = M;
  }
  __syncthreads();
  float ze = (t < NTK) ? g_Zt[b*NTK + t]*expf(m - sM) : 0.f;
  float zz = warpSum(ze);
  if (lane==0) s_red[warp] = zz;
  __syncthreads();
  if (t==0){
    float Z = 0.f;
    #pragma unroll
    for (int r=0;r<8;r++) Z += s_red[r];
    sZ = Z;
  }
  __syncthreads();
  if (t < NTK) s_alpha[t] = expf(m - sM)/sZ;
  __syncthreads();

  // --- xk[c] = sum_j xkp[j][c] * alpha[j] ---
  float xk = 0.f;
  #pragma unroll 8
  for (int j=0;j<NTK;j++)
    xk = fmaf(g_xkp[((size_t)(b*NTK+j))*Cdim + t], s_alpha[j], xk);
  s_xk[t] = xk;
  __syncthreads();

  // --- cf = vw @ xk + vb ---
  float cf = vb[t];
  #pragma unroll 8
  for (int c=0;c<Cdim;c++) cf = fmaf(vw[t*Cdim + c], s_xk[c], cf);
  g_cf[b*Cdim + t] = cf;
}

// ---------------- K3: epilogue (computes s inline) ----------------
// grid (64, Bdim), 256 thr. Block: all 256 channels x 256 px (2 rows).
__global__ __launch_bounds__(256)
void k3_final(const float* __restrict__ x, float* __restrict__ out,
              const float* __restrict__ b3p){
  const int jt = blockIdx.x, b = blockIdx.y;
  const int t = threadIdx.x;
  __shared__ float4 s_s[64];
  __shared__ float  s_cf[Cdim];

  s_cf[t] = g_cf[b*Cdim + t];
  if (t < 64){
    const float b3 = b3p[0];
    int n = jt*256 + 4*t;
    float ah = g_ah[b*Hdim + (n>>7)];
    int w0 = n & 127;
    float4 t3 = *(const float4*)(g_t3s + (size_t)b*HW + n);
    float4 s;
    s.x = sigmoidf_((ah + g_aw[b*Wdim + w0+0])*t3.x + b3);
    s.y = sigmoidf_((ah + g_aw[b*Wdim + w0+1])*t3.y + b3);
    s.z = sigmoidf_((ah + g_aw[b*Wdim + w0+2])*t3.z + b3);
    s.w = sigmoidf_((ah + g_aw[b*Wdim + w0+3])*t3.w + b3);
    s_s[t] = s;
  }
  __syncthreads();

  const int c0 = t>>6, f4i = t&63;
  const float4 sv = s_s[f4i];
  const size_t base0 = (size_t)(b*Cdim)*4096 + jt*64 + f4i;
  const float4* x4 = (const float4*)x;
  float4* o4 = (float4*)out;
  #pragma unroll 4
  for (int it=0; it<64; it++){
    int c = it*4 + c0;
    float cf = s_cf[c];
    size_t idx = base0 + (size_t)c*4096;
    float4 xv = x4[idx];
    float4 o;
    o.x = fmaf(sv.x, cf, xv.x);
    o.y = fmaf(sv.y, cf, xv.y);
    o.z = fmaf(sv.z, cf, xv.z);
    o.w = fmaf(sv.w, cf, xv.w);
    o4[idx] = o;
  }
}

// ---------------- launch ----------------
extern "C" void kernel_launch(void* const* d_in, const int* in_sizes, int n_in,
                              void* d_out, int out_size){
  const float* x  = (const float*)d_in[0];
  const float* vw = (const float*)d_in[1];
  const float* vb = (const float*)d_in[2];
  const float* kw = (const float*)d_in[3];
  const float* kb = (const float*)d_in[4];
  const float* w1 = (const float*)d_in[5];
  const float* b1 = (const float*)d_in[6];
  const float* w2 = (const float*)d_in[7];
  const float* b2 = (const float*)d_in[8];
  const float* w3 = (const float*)d_in[9];
  const float* b3 = (const float*)d_in[10];
  float* out = (float*)d_out;

  cudaFuncSetAttribute(k1_main, cudaFuncAttributeMaxDynamicSharedMemorySize, K1_SMEM);

  k0_init<<<1,256>>>(vw, vb, w3);
  k1_main<<<dim3(NTK,Bdim),512,K1_SMEM>>>(x, kw, kb, w1, b1);
  k2_combine<<<Bdim,256>>>(vw, vb, w2, b2);
  k3_final<<<dim3(64,Bdim),256>>>(x, out, b3);
}